// round 4
// baseline (speedup 1.0000x reference)
#include <cuda_runtime.h>
#include <cstdint>

// AnchorMatcher: N anchors x M gt boxes -> packed float32 out[6N]:
//   [0,N): cls targets, [N,5N): reg targets (float4), [5N,6N): pos mask 0/1.

#define MAXN   262144   // >= 200000
#define MAXM   128
#define POS_THR 0.5f
#define NEG_THR 0.4f
#define APT     4        // anchors per thread
#define TPB     256      // threads per block
#define APB     (APT * TPB)

// Scratch (no allocations allowed -> __device__ globals; zero-init at load)
__device__ int                g_midx[MAXN];
__device__ unsigned long long g_packed[MAXM];  // per-gt (iou_bits<<32)|(~anchor_idx)

// ---------------------------------------------------------------------------
// Kernel A: fused IoU + epilogue, 4 anchors per thread.
//   per-anchor: max IoU + argmax (natural j order, strict > = first-index
//               tie-break, matching jnp.argmax(axis=1)); writes cls/reg/mask.
//   per-gt:     thread-max of 4 -> gated warp redux -> <=1 shared atomic per
//               (warp,j) -> one global atomicMax per (block,j). Lane order ==
//               anchor order, so lowest-matching-lane + earliest in-thread
//               anchor == smallest anchor index (jnp.argmax(axis=0) tie-break).
// ---------------------------------------------------------------------------
__global__ __launch_bounds__(TPB) void k_iou(
    const float4* __restrict__ anchors,
    const float4* __restrict__ gts,
    const int*    __restrict__ labels,
    float*        __restrict__ out,
    int N, int M)
{
    __shared__ float4             sg[MAXM];   // gt boxes
    __shared__ float              sga[MAXM];  // gt areas
    __shared__ int                slab[MAXM]; // gt labels
    __shared__ unsigned long long sp[MAXM];   // per-gt packed best (block)

    const int tid = threadIdx.x;
    if (tid < M) {
        float4 g = gts[tid];
        sg[tid]   = g;
        sga[tid]  = (g.z - g.x) * (g.w - g.y);
        slab[tid] = labels[tid];
        sp[tid]   = 0ULL;
    }
    __syncthreads();

    const unsigned lane = tid & 31u;
    const int i0 = (blockIdx.x * TPB + tid) * APT;  // first of 4 consecutive anchors

    float4 a[APT];
    float  areaA[APT];
    bool   valid[APT];
    #pragma unroll
    for (int k = 0; k < APT; ++k) {
        valid[k] = (i0 + k) < N;
        a[k] = valid[k] ? anchors[i0 + k] : make_float4(0.f, 0.f, 0.f, 0.f);
        areaA[k] = (a[k].z - a[k].x) * (a[k].w - a[k].y);
    }

    float best[APT];
    int   bj[APT];
    #pragma unroll
    for (int k = 0; k < APT; ++k) { best[k] = -1.0f; bj[k] = 0; }

    #pragma unroll 2
    for (int j = 0; j < M; ++j) {
        const float4 g  = sg[j];
        const float  ga = sga[j];

        unsigned bits[APT];
        #pragma unroll
        for (int k = 0; k < APT; ++k) {
            const float w = fmaxf(fminf(a[k].z, g.z) - fmaxf(a[k].x, g.x), 0.0f);
            const float h = fmaxf(fminf(a[k].w, g.w) - fmaxf(a[k].y, g.y), 0.0f);
            const float inter = w * h;
            // IEEE RN division: threshold/argmax decisions must match XLA's
            // rounded quotients bitwise, independent of compiler flags.
            const float iou = __fdiv_rn(inter, (areaA[k] + ga) - inter);
            if (iou > best[k]) { best[k] = iou; bj[k] = j; }  // strict > = first idx
            bits[k] = valid[k] ? __float_as_uint(iou) : 0u;   // iou>=0 -> monotone
        }

        // thread-level max of the 4 anchors
        unsigned tb = bits[0];
        #pragma unroll
        for (int k = 1; k < APT; ++k) tb = (bits[k] > tb) ? bits[k] : tb;

        // Gate on the atomic slot's own high word (monotone under atomicMax;
        // a stale low read only admits extra work, never skips a needed update).
        const unsigned cur = reinterpret_cast<const unsigned*>(&sp[j])[1];
        if (__any_sync(0xffffffffu, tb >= cur)) {
            const unsigned wmax = __reduce_max_sync(0xffffffffu, tb);
            const unsigned mk   = __ballot_sync(0xffffffffu, tb == wmax);
            if (lane == (unsigned)(__ffs(mk) - 1)) {
                int off = 0;                       // earliest anchor with max bits
                #pragma unroll
                for (int k = APT - 1; k >= 1; --k) if (bits[k - 1] != wmax || off == 0)
                    ; // (placeholder to keep unroll shape; real select below)
                off = (bits[0] == wmax) ? 0 : (bits[1] == wmax) ? 1
                    : (bits[2] == wmax) ? 2 : 3;
                const unsigned inv = 0xFFFFFFFFu - (unsigned)(i0 + off);
                atomicMax(&sp[j], ((unsigned long long)wmax << 32) | inv);
            }
        }
    }

    // ---- epilogue: write outputs directly (k_force patches <=M rows) ----
    #pragma unroll
    for (int k = 0; k < APT; ++k) {
        if (!valid[k]) continue;
        const int i = i0 + k;
        g_midx[i] = bj[k];

        const bool pos = (best[k] >= POS_THR);
        out[i] = pos ? (float)slab[bj[k]] : (best[k] < NEG_THR ? 0.0f : -1.0f);

        float4 r = make_float4(0.0f, 0.0f, 0.0f, 0.0f);
        if (pos) {
            const float eps = 1.1920929e-7f;  // FLT_EPSILON (jnp.finfo eps)
            const float4 g = sg[bj[k]];
            const float aw = fmaxf(a[k].z - a[k].x, eps);
            const float ah = fmaxf(a[k].w - a[k].y, eps);
            r.x = __fdiv_rn((g.x + g.z) * 0.5f - (a[k].x + a[k].z) * 0.5f, aw);
            r.y = __fdiv_rn((g.y + g.w) * 0.5f - (a[k].y + a[k].w) * 0.5f, ah);
            r.z = logf(__fdiv_rn(g.z - g.x, aw));
            r.w = logf(__fdiv_rn(g.w - g.y, ah));
            // WEIGHTS = (1,1,1,1) -> identity multiply skipped.
        }
        reinterpret_cast<float4*>(out + N)[i] = r;  // out+N 16B-aligned (N%4==0)
        out[5 * N + i] = pos ? 1.0f : 0.0f;
    }

    __syncthreads();
    if (tid < M) {
        const unsigned long long v = sp[tid];
        if (v) atomicMax(&g_packed[tid], v);
    }
}

// ---------------------------------------------------------------------------
// Kernel F: patch forced-positive anchors (<=M rows), reset g_packed.
//   Idempotent for already-positive anchors; duplicate gt winners write
//   identical values (j = g_midx[a] either way).
// ---------------------------------------------------------------------------
__global__ void k_force(
    const float4* __restrict__ anchors,
    const float4* __restrict__ gts,
    const int*    __restrict__ labels,
    float*        __restrict__ out,
    int N, int M)
{
    const int t = threadIdx.x;
    if (t >= M) return;

    const unsigned long long v = g_packed[t];
    g_packed[t] = 0ULL;                       // consume-and-reset for next replay

    // v==0 can only mean an all-zero IoU column that nothing recorded;
    // reference argmax then picks anchor 0.
    unsigned ai = v ? (0xFFFFFFFFu - (unsigned)(v & 0xFFFFFFFFull)) : 0u;
    if (ai >= (unsigned)N) return;

    const int j = g_midx[ai];
    out[ai] = (float)labels[j];

    const float eps = 1.1920929e-7f;
    const float4 a = anchors[ai];
    const float4 g = gts[j];
    const float aw = fmaxf(a.z - a.x, eps);
    const float ah = fmaxf(a.w - a.y, eps);
    float4 r;
    r.x = __fdiv_rn((g.x + g.z) * 0.5f - (a.x + a.z) * 0.5f, aw);
    r.y = __fdiv_rn((g.y + g.w) * 0.5f - (a.y + a.w) * 0.5f, ah);
    r.z = logf(__fdiv_rn(g.z - g.x, aw));
    r.w = logf(__fdiv_rn(g.w - g.y, ah));
    reinterpret_cast<float4*>(out + N)[ai] = r;

    out[5 * N + ai] = 1.0f;
}

// ---------------------------------------------------------------------------
extern "C" void kernel_launch(void* const* d_in, const int* in_sizes, int n_in,
                              void* d_out, int out_size)
{
    const float4* anchors = (const float4*)d_in[0];
    const float4* gts     = (const float4*)d_in[1];
    const int*    labels  = (const int*)d_in[2];
    float*        out     = (float*)d_out;

    const int N = in_sizes[0] / 4;
    const int M = in_sizes[1] / 4;   // 128

    const int blocks = (N + APB - 1) / APB;

    k_iou  <<<blocks, TPB>>>(anchors, gts, labels, out, N, M);
    k_force<<<1, 128>>>(anchors, gts, labels, out, N, M);
}

// round 8
// speedup vs baseline: 1.3652x; 1.3652x over previous
#include <cuda_runtime.h>
#include <cstdint>

// AnchorMatcher: N anchors x M gt boxes -> packed float32 out[6N]:
//   [0,N): cls targets, [N,5N): reg targets (float4), [5N,6N): pos mask 0/1.
// Single fused kernel: IoU pass + epilogue + last-block forced-positive patch.

#define MAXN   262144   // >= 200000
#define MAXM   128
#define POS_THR 0.5f
#define NEG_THR 0.4f
#define APT     2        // anchors per thread
#define TPB     256      // threads per block
#define APB     (APT * TPB)

// Scratch (no allocations allowed -> __device__ globals; zero-init at load)
__device__ int                g_midx[MAXN];
__device__ unsigned long long g_packed[MAXM];  // per-gt (iou_bits<<32)|(~anchor_idx)
__device__ unsigned int       g_ticket;        // last-block-done counter

__global__ __launch_bounds__(TPB) void k_iou(
    const float4* __restrict__ anchors,
    const float4* __restrict__ gts,
    const int*    __restrict__ labels,
    float*        __restrict__ out,
    int N, int M)
{
    __shared__ float4             sg[MAXM];   // gt boxes
    __shared__ float              sga[MAXM];  // gt areas
    __shared__ int                slab[MAXM]; // gt labels
    __shared__ unsigned long long sp[MAXM];   // per-gt packed best (block)
    __shared__ bool               s_last;     // last-block flag

    const int tid = threadIdx.x;
    if (tid < M) {
        float4 g = gts[tid];
        sg[tid]   = g;
        sga[tid]  = (g.z - g.x) * (g.w - g.y);
        slab[tid] = labels[tid];
        sp[tid]   = 0ULL;
    }
    __syncthreads();

    const int i0 = (blockIdx.x * TPB + tid) * APT;  // 2 consecutive anchors (even)

    float4   a[APT];
    float    areaA[APT];
    unsigned inv[APT];
    bool     valid[APT];
    #pragma unroll
    for (int k = 0; k < APT; ++k) {
        valid[k] = (i0 + k) < N;
        a[k]     = valid[k] ? anchors[i0 + k] : make_float4(0.f, 0.f, 0.f, 0.f);
        areaA[k] = (a[k].z - a[k].x) * (a[k].w - a[k].y);
        // invalid lanes get inv=0 so their packed key (0) can never win
        inv[k]   = valid[k] ? (0xFFFFFFFFu - (unsigned)(i0 + k)) : 0u;
    }

    float best[APT];
    int   bj[APT];
    #pragma unroll
    for (int k = 0; k < APT; ++k) { best[k] = -1.0f; bj[k] = 0; }

    // ---------------- hot loop: branchless, collective-free ----------------
    #pragma unroll 4
    for (int j = 0; j < M; ++j) {
        const float4 g  = sg[j];
        const float  ga = sga[j];

        unsigned bits[APT];
        #pragma unroll
        for (int k = 0; k < APT; ++k) {
            const float w = fmaxf(fminf(a[k].z, g.z) - fmaxf(a[k].x, g.x), 0.0f);
            const float h = fmaxf(fminf(a[k].w, g.w) - fmaxf(a[k].y, g.y), 0.0f);
            const float inter = w * h;
            // IEEE RN division: XLA emits div.rn.f32; every threshold/argmax
            // decision must match its rounded quotient bitwise.
            const float iou = __fdiv_rn(inter, (areaA[k] + ga) - inter);
            if (iou > best[k]) { best[k] = iou; bj[k] = j; }  // strict > = first idx
            bits[k] = valid[k] ? __float_as_uint(iou) : 0u;   // iou>=0 -> monotone
        }

        // thread-best of 2; '>=' keeps the earlier (lower) index on ties
        const bool     first = (bits[0] >= bits[1]);
        const unsigned tb    = first ? bits[0] : bits[1];
        const unsigned tinv  = first ? inv[0]  : inv[1];

        // Gate on the slot's own high word: monotone under atomicMax, so a
        // stale (lower) read only admits extra atomics, never misses one.
        const unsigned cur = reinterpret_cast<const unsigned*>(&sp[j])[1];
        if (tb >= cur)
            atomicMax(&sp[j], ((unsigned long long)tb << 32) | tinv);
    }

    // ---------------- epilogue: direct, packed output writes ----------------
    if (valid[0]) {
        float cls[APT], msk[APT];
        #pragma unroll
        for (int k = 0; k < APT; ++k) {
            const int i = i0 + k;
            if (!valid[k]) { cls[k] = 0.f; msk[k] = 0.f; continue; }
            g_midx[i] = bj[k];

            const bool pos = (best[k] >= POS_THR);
            cls[k] = pos ? (float)slab[bj[k]] : (best[k] < NEG_THR ? 0.0f : -1.0f);
            msk[k] = pos ? 1.0f : 0.0f;

            float4 r = make_float4(0.0f, 0.0f, 0.0f, 0.0f);
            if (pos) {
                const float eps = 1.1920929e-7f;  // FLT_EPSILON (jnp.finfo eps)
                const float4 g = sg[bj[k]];
                const float aw = fmaxf(a[k].z - a[k].x, eps);
                const float ah = fmaxf(a[k].w - a[k].y, eps);
                r.x = __fdiv_rn((g.x + g.z) * 0.5f - (a[k].x + a[k].z) * 0.5f, aw);
                r.y = __fdiv_rn((g.y + g.w) * 0.5f - (a[k].y + a[k].w) * 0.5f, ah);
                r.z = logf(__fdiv_rn(g.z - g.x, aw));
                r.w = logf(__fdiv_rn(g.w - g.y, ah));
                // WEIGHTS = (1,1,1,1) -> identity multiply skipped.
            }
            reinterpret_cast<float4*>(out + N)[i] = r;  // out+N 16B-aligned
        }

        if (valid[1]) {
            // i0 even -> 8B-aligned float2 stores (one STG.64 each)
            *reinterpret_cast<float2*>(out + i0)         = make_float2(cls[0], cls[1]);
            *reinterpret_cast<float2*>(out + 5 * N + i0) = make_float2(msk[0], msk[1]);
        } else {
            out[i0]         = cls[0];
            out[5 * N + i0] = msk[0];
        }
    }

    // ---------------- flush per-gt partials, elect last block ----------------
    __syncthreads();
    if (tid < M) {
        const unsigned long long v = sp[tid];
        if (v) atomicMax(&g_packed[tid], v);
    }
    __threadfence();                 // publish outputs + g_midx + g_packed
    __syncthreads();
    if (tid == 0)
        s_last = (atomicAdd(&g_ticket, 1u) == (unsigned)(gridDim.x - 1));
    __syncthreads();

    // ---------------- last block: patch forced positives ----------------
    if (s_last) {
        __threadfence();             // acquire side: see all blocks' writes
        if (tid == 0) g_ticket = 0;  // reset for next graph replay
        if (tid < M) {
            const unsigned long long v = g_packed[tid];
            g_packed[tid] = 0ULL;    // consume-and-reset for next replay

            // v==0 would mean an all-zero IoU column nothing recorded;
            // reference argmax then picks anchor 0.
            const unsigned ai = v ? (0xFFFFFFFFu - (unsigned)(v & 0xFFFFFFFFull)) : 0u;
            if (ai < (unsigned)N) {
                const int j = g_midx[ai];
                out[ai] = (float)slab[j];        // scalar: never clobbers neighbor

                const float eps = 1.1920929e-7f;
                const float4 av = anchors[ai];
                const float4 g  = sg[j];         // gt tile still live in this block
                const float aw = fmaxf(av.z - av.x, eps);
                const float ah = fmaxf(av.w - av.y, eps);
                float4 r;
                r.x = __fdiv_rn((g.x + g.z) * 0.5f - (av.x + av.z) * 0.5f, aw);
                r.y = __fdiv_rn((g.y + g.w) * 0.5f - (av.y + av.w) * 0.5f, ah);
                r.z = logf(__fdiv_rn(g.z - g.x, aw));
                r.w = logf(__fdiv_rn(g.w - g.y, ah));
                reinterpret_cast<float4*>(out + N)[ai] = r;

                out[5 * N + ai] = 1.0f;
            }
        }
    }
}

// ---------------------------------------------------------------------------
extern "C" void kernel_launch(void* const* d_in, const int* in_sizes, int n_in,
                              void* d_out, int out_size)
{
    const float4* anchors = (const float4*)d_in[0];
    const float4* gts     = (const float4*)d_in[1];
    const int*    labels  = (const int*)d_in[2];
    float*        out     = (float*)d_out;

    const int N = in_sizes[0] / 4;
    const int M = in_sizes[1] / 4;   // 128

    const int blocks = (N + APB - 1) / APB;

    k_iou<<<blocks, TPB>>>(anchors, gts, labels, out, N, M);
}